// round 10
// baseline (speedup 1.0000x reference)
#include <cuda_runtime.h>
#include <cuda_fp16.h>
#include <cstdint>

// Problem dims (fixed): x [4,2048,2048] f32, w_int [2048,2048] i32,
// w_scales/w_zeros [2048,64] f32. out [8192,2048] f32.
#define DIN    2048
#define DOUT   2048
#define MAXM   8192
#define NGRP   64            // DIN / 32

#define BM 128
#define BN 128
#define BK 64                // int8 elems per chunk: 64 bytes per row, 2 groups
#define STAGES 3
#define TPB 256
#define SA_BYTES (BM * 64)   // 8 KB
#define SB_BYTES (BN * 64)   // 8 KB
#define SS_BYTES 1024        // 2 groups x 128 floats
#define SMEM_B_OFF (STAGES * SA_BYTES)
#define SMEM_S_OFF (SMEM_B_OFF + STAGES * SB_BYTES)
#define SMEM_TOTAL (SMEM_S_OFF + STAGES * SS_BYTES)   // 52224 B -> 2 CTAs/SM

// Scratch (__device__ globals: allocation-free rule)
__device__ int8_t g_q[(size_t)MAXM * DIN];     // per-token int8 q
__device__ float  g_sx[MAXM];                  // per-token scale
__device__ float  g_szp[MAXM];                 // scale * zero_point
__device__ int8_t g_wi8[(size_t)DOUT * DIN];   // w' = rint(w - z_g), int8
__device__ float  g_st[(size_t)NGRP * DOUT];   // scales transposed [g][o]
__device__ float  g_wtot[DOUT];                // sum_g s_g * colsum_g(w')

// ---------------------------------------------------------------------------
// Kernel 1: per-token dynamic quant -> int8 q + (sx, sx*zp)
// ---------------------------------------------------------------------------
__global__ void __launch_bounds__(256) quant_x_kernel(const float* __restrict__ x) {
    const int row  = blockIdx.x * 8 + (threadIdx.x >> 5);
    const int lane = threadIdx.x & 31;
    const float4* xr4 = reinterpret_cast<const float4*>(x + (size_t)row * DIN);

    float4 v[16];                        // whole row across the warp
#pragma unroll
    for (int c = 0; c < 4; c++)
#pragma unroll
        for (int j = 0; j < 4; j++)
            v[c * 4 + j] = xr4[c * 128 + lane * 4 + j];

    float mn = 0.0f, mx = 0.0f;          // init 0 implements min(.,0)/max(.,0)
#pragma unroll
    for (int i = 0; i < 16; i++) {
        mn = fminf(mn, fminf(fminf(v[i].x, v[i].y), fminf(v[i].z, v[i].w)));
        mx = fmaxf(mx, fmaxf(fmaxf(v[i].x, v[i].y), fmaxf(v[i].z, v[i].w)));
    }
#pragma unroll
    for (int o = 16; o; o >>= 1) {
        mn = fminf(mn, __shfl_xor_sync(0xffffffffu, mn, o));
        mx = fmaxf(mx, __shfl_xor_sync(0xffffffffu, mx, o));
    }
    float scale = __fdiv_rn(mx - mn, 255.0f);
    scale = fmaxf(scale, 1.1920929e-07f);          // float32 eps
    float zp = -128.0f - rintf(__fdiv_rn(mn, scale));
    zp = fminf(fmaxf(zp, -128.0f), 127.0f);
    if (lane == 0) { g_sx[row] = scale; g_szp[row] = scale * zp; }

    int8_t* qrow = g_q + (size_t)row * DIN;
#pragma unroll
    for (int c = 0; c < 4; c++) {
        uint32_t p[4];
#pragma unroll
        for (int j = 0; j < 4; j++) {
            float4 vv = v[c * 4 + j];
            int q0 = (int)(fminf(fmaxf(rintf(__fdiv_rn(vv.x, scale)) + zp, -128.0f), 127.0f));
            int q1 = (int)(fminf(fmaxf(rintf(__fdiv_rn(vv.y, scale)) + zp, -128.0f), 127.0f));
            int q2 = (int)(fminf(fmaxf(rintf(__fdiv_rn(vv.z, scale)) + zp, -128.0f), 127.0f));
            int q3 = (int)(fminf(fmaxf(rintf(__fdiv_rn(vv.w, scale)) + zp, -128.0f), 127.0f));
            p[j] = (uint32_t)(q0 & 255) | ((uint32_t)(q1 & 255) << 8)
                 | ((uint32_t)(q2 & 255) << 16) | ((uint32_t)(q3 & 255) << 24);
        }
        *reinterpret_cast<uint4*>(qrow + c * 512 + lane * 16) =
            make_uint4(p[0], p[1], p[2], p[3]);
    }
}

// ---------------------------------------------------------------------------
// Kernel 2: W prep: w' int8, wtot[o] = sum_g s_g * colsum_g(w')
// ---------------------------------------------------------------------------
__global__ void __launch_bounds__(256) wprep_kernel(const int* __restrict__ w,
                                                    const float* __restrict__ s,
                                                    const float* __restrict__ z) {
    const int o    = blockIdx.x * 8 + (threadIdx.x >> 5);
    const int lane = threadIdx.x & 31;
    const int ga = lane * 2;                       // lane covers groups ga, ga+1
    const float sa = s[o * NGRP + ga], sb = s[o * NGRP + ga + 1];
    const float za = z[o * NGRP + ga], zb = z[o * NGRP + ga + 1];

    const int4* wr = reinterpret_cast<const int4*>(w + (size_t)o * DIN + lane * 64);
    int8_t* orow = g_wi8 + (size_t)o * DIN + lane * 64;
    int csa = 0, csb = 0;
#pragma unroll
    for (int c = 0; c < 4; c++) {
        uint32_t p[4];
#pragma unroll
        for (int j = 0; j < 4; j++) {
            int4 w4 = wr[c * 4 + j];
            float zg = (c < 2) ? za : zb;          // elems c*16.. : first 32 -> ga
            int q0 = max(-128, min(127, __float2int_rn((float)w4.x - zg)));
            int q1 = max(-128, min(127, __float2int_rn((float)w4.y - zg)));
            int q2 = max(-128, min(127, __float2int_rn((float)w4.z - zg)));
            int q3 = max(-128, min(127, __float2int_rn((float)w4.w - zg)));
            int ssum = q0 + q1 + q2 + q3;
            if (c < 2) csa += ssum; else csb += ssum;
            p[j] = (uint32_t)(q0 & 255) | ((uint32_t)(q1 & 255) << 8)
                 | ((uint32_t)(q2 & 255) << 16) | ((uint32_t)(q3 & 255) << 24);
        }
        *reinterpret_cast<uint4*>(orow + c * 16) = make_uint4(p[0], p[1], p[2], p[3]);
    }
    float wt = sa * (float)csa + sb * (float)csb;
#pragma unroll
    for (int off = 16; off; off >>= 1)
        wt += __shfl_xor_sync(0xffffffffu, wt, off);
    if (lane == 0) g_wtot[o] = wt;
}

// Kernel 2b: transpose scales -> g_st[g][o] (contiguous in o for cp.async)
__global__ void __launch_bounds__(256) st_kernel(const float* __restrict__ s) {
    const int o = blockIdx.x * 256 + threadIdx.x;
    const int g = blockIdx.y;
    g_st[(size_t)g * DOUT + o] = s[(size_t)o * NGRP + g];
}

// ---------------------------------------------------------------------------
// Kernel 3: int8 IMMA GEMM with per-group fp32 scale folding
// ---------------------------------------------------------------------------
__device__ __forceinline__ uint32_t sw(uint32_t off) {
    return off ^ ((off >> 3) & 0x70);      // bits[6:4] ^= bits[9:7]
}

__device__ __forceinline__ void cp_async16(uint32_t saddr, const void* gaddr) {
    asm volatile("cp.async.cg.shared.global [%0], [%1], 16;"
                 :: "r"(saddr), "l"(gaddr) : "memory");
}

// Load one K-chunk: A 128x64 i8, B 128x64 i8, scales 2x128 f32. Always commits.
__device__ __forceinline__ void load_stage(uint32_t sbase, int st,
                                           const int8_t* gA, const int8_t* gB,
                                           const float* gS, int kt, int T) {
    if (kt < T) {
        const int tid = threadIdx.x;
        const int k0 = kt * BK;
#pragma unroll
        for (int it = 0; it < 2; it++) {
            int c = it * TPB + tid;            // 512 chunks of 16B per operand
            int row = c >> 2, col = c & 3;
            uint32_t off = sw((uint32_t)(row * 64 + col * 16));
            cp_async16(sbase + st * SA_BYTES + off,
                       gA + (size_t)row * DIN + k0 + col * 16);
            cp_async16(sbase + SMEM_B_OFF + st * SB_BYTES + off,
                       gB + (size_t)row * DIN + k0 + col * 16);
        }
        if (tid < 64) {
            int grp = tid >> 5, cc = tid & 31;
            cp_async16(sbase + SMEM_S_OFF + st * SS_BYTES + grp * 512 + cc * 16,
                       gS + (size_t)(2 * kt + grp) * DOUT + cc * 4);
        }
    }
    asm volatile("cp.async.commit_group;" ::: "memory");
}

__global__ void __launch_bounds__(TPB, 2)
gemm_i8_kernel(float* __restrict__ out, int M) {
    extern __shared__ char smem[];
    const uint32_t sbase = (uint32_t)__cvta_generic_to_shared(smem);
    const int tid = threadIdx.x;
    const int lane = tid & 31, wid = tid >> 5;
    const int wm = wid & 3;                 // warp M index (x32)
    const int wn = wid >> 2;                // warp N index (x64)
    const int n0 = blockIdx.x * BN;
    const int m0 = blockIdx.y * BM;

    const int8_t* gA = g_q + (size_t)m0 * DIN;
    const int8_t* gB = g_wi8 + (size_t)n0 * DIN;
    const float*  gS = g_st + n0;
    const int T = DIN / BK;                 // 32

    load_stage(sbase, 0, gA, gB, gS, 0, T);
    load_stage(sbase, 1, gA, gB, gS, 1, T);

    float facc[2][8][4];
#pragma unroll
    for (int i = 0; i < 2; i++)
#pragma unroll
        for (int j = 0; j < 8; j++)
#pragma unroll
            for (int k = 0; k < 4; k++) facc[i][j][k] = 0.0f;

    // ldmatrix row/column-within-row mapping (byte-identical to s8 k32 frags)
    const int lrow = (lane & 7) + ((lane >> 3) & 1) * 8;
    const int lkb  = (lane >> 4) * 16;

    int st = 0;
    for (int t = 0; t < T; t++) {
        asm volatile("cp.async.wait_group 1;" ::: "memory");
        __syncthreads();
        const uint32_t abase = sbase + st * SA_BYTES;
        const uint32_t bbase = sbase + SMEM_B_OFF + st * SB_BYTES;
        const uint32_t ssb   = sbase + SMEM_S_OFF + st * SS_BYTES
                             + (uint32_t)((wn * 64 + (lane & 3) * 2) * 4);

#pragma unroll
        for (int grp = 0; grp < 2; grp++) {
            const int kb = grp * 32 + lkb;
            uint32_t a[2][4], b[4][4];
#pragma unroll
            for (int mb = 0; mb < 2; mb++) {
                int row = wm * 32 + mb * 16 + lrow;
                uint32_t addr = abase + sw((uint32_t)(row * 64 + kb));
                asm volatile("ldmatrix.sync.aligned.m8n8.x4.shared.b16 {%0,%1,%2,%3}, [%4];"
                             : "=r"(a[mb][0]), "=r"(a[mb][1]),
                               "=r"(a[mb][2]), "=r"(a[mb][3]) : "r"(addr));
            }
#pragma unroll
            for (int nb = 0; nb < 4; nb++) {
                int row = wn * 64 + nb * 16 + lrow;
                uint32_t addr = bbase + sw((uint32_t)(row * 64 + kb));
                asm volatile("ldmatrix.sync.aligned.m8n8.x4.shared.b16 {%0,%1,%2,%3}, [%4];"
                             : "=r"(b[nb][0]), "=r"(b[nb][1]),
                               "=r"(b[nb][2]), "=r"(b[nb][3]) : "r"(addr));
            }
#pragma unroll
            for (int nb8 = 0; nb8 < 8; nb8++) {
                float scx, scy;
                asm volatile("ld.shared.v2.f32 {%0,%1}, [%2];"
                             : "=f"(scx), "=f"(scy)
                             : "r"(ssb + grp * 512 + nb8 * 32));
                uint32_t b0 = b[nb8 >> 1][nb8 & 1], b1 = b[nb8 >> 1][(nb8 & 1) + 2];
#pragma unroll
                for (int mb = 0; mb < 2; mb++) {
                    int d0, d1, d2, d3;
                    asm volatile(
                        "mma.sync.aligned.m16n8k32.row.col.s32.s8.s8.s32 "
                        "{%0,%1,%2,%3}, {%4,%5,%6,%7}, {%8,%9}, {%10,%11,%12,%13};"
                        : "=r"(d0), "=r"(d1), "=r"(d2), "=r"(d3)
                        : "r"(a[mb][0]), "r"(a[mb][1]), "r"(a[mb][2]), "r"(a[mb][3]),
                          "r"(b0), "r"(b1), "r"(0), "r"(0), "r"(0), "r"(0));
                    float* c = facc[mb][nb8];
                    c[0] += scx * (float)d0;
                    c[1] += scy * (float)d1;
                    c[2] += scx * (float)d2;
                    c[3] += scy * (float)d3;
                }
            }
        }
        // Tail load: writes stage (t+2)%3 == (t-1)%3, only read by warps that
        // already passed this chunk's barrier; the load aliasing stage t sits
        // behind iteration t+1's barrier. One sync per chunk is sufficient.
        int nst = st + 2; if (nst >= STAGES) nst -= STAGES;
        load_stage(sbase, nst, gA, gB, gS, t + 2, T);
        if (++st == STAGES) st = 0;
    }

    // Epilogue: out = sx*facc - (sx*zp)*wtot[n]
#pragma unroll
    for (int mb = 0; mb < 2; mb++) {
        const int mrow = m0 + wm * 32 + mb * 16 + (lane >> 2);
        const float sx0 = g_sx[mrow],     zp0 = g_szp[mrow];
        const float sx1 = g_sx[mrow + 8], zp1 = g_szp[mrow + 8];
        float* o0 = out + (size_t)mrow * DOUT + n0 + wn * 64 + (lane & 3) * 2;
        float* o1 = o0 + (size_t)8 * DOUT;
        const float* wt = g_wtot + n0 + wn * 64 + (lane & 3) * 2;
#pragma unroll
        for (int nb8 = 0; nb8 < 8; nb8++) {
            float2 w2 = *reinterpret_cast<const float2*>(wt + nb8 * 8);
            float* c = facc[mb][nb8];
            *reinterpret_cast<float2*>(o0 + nb8 * 8) =
                make_float2(sx0 * c[0] - zp0 * w2.x, sx0 * c[1] - zp0 * w2.y);
            *reinterpret_cast<float2*>(o1 + nb8 * 8) =
                make_float2(sx1 * c[2] - zp1 * w2.x, sx1 * c[3] - zp1 * w2.y);
        }
    }
}

// ---------------------------------------------------------------------------
extern "C" void kernel_launch(void* const* d_in, const int* in_sizes, int n_in,
                              void* d_out, int out_size) {
    const float* x     = (const float*)d_in[0];
    const int*   w_int = (const int*)d_in[1];
    const float* w_s   = (const float*)d_in[2];
    const float* w_z   = (const float*)d_in[3];
    float* out = (float*)d_out;

    const int M = in_sizes[0] / DIN;   // 8192 tokens

    cudaFuncSetAttribute(gemm_i8_kernel,
                         cudaFuncAttributeMaxDynamicSharedMemorySize, SMEM_TOTAL);

    quant_x_kernel<<<M / 8, 256>>>(x);
    wprep_kernel<<<DOUT / 8, 256>>>(w_int, w_s, w_z);
    st_kernel<<<dim3(DOUT / 256, NGRP), 256>>>(w_s);
    gemm_i8_kernel<<<dim3(DOUT / BN, M / BM), TPB, SMEM_TOTAL>>>(out, M);
}

// round 12
// speedup vs baseline: 2.5897x; 2.5897x over previous
#include <cuda_runtime.h>
#include <cuda_fp16.h>
#include <cstdint>

// Problem dims (fixed): x [4,2048,2048] f32, w_int [2048,2048] i32,
// w_scales/w_zeros [2048,64] f32. out [8192,2048] f32.
#define DIN    2048
#define DOUT   2048
#define MAXM   8192

#define BM 128
#define BN 128
#define BK 64                 // fp16 elems per chunk: 128 bytes per row
#define STAGES 3
#define TPB 256
#define STAGE_A_BYTES (BM * 128)      // 16 KB
#define STAGE_B_BYTES (BN * 128)      // 16 KB
#define SMEM_B_OFF (STAGES * STAGE_A_BYTES)
#define SMEM_TOTAL (STAGES * (STAGE_A_BYTES + STAGE_B_BYTES))   // 96 KB -> 2 CTAs/SM

// Scratch (__device__ globals: allocation-free rule)
__device__ __half g_qd[(size_t)MAXM * DIN];    // (q - zp): integer, exact in fp16
__device__ float  g_sx[MAXM];                  // per-token scale
__device__ __half g_wdq[(size_t)DOUT * DIN];   // dequantized weights fp16

// ---------------------------------------------------------------------------
// Kernel 1: per-token dynamic quant, one warp per row, row in registers,
// reciprocal-multiply instead of per-element division.
// qd = clip(rint(x/s)+zp,-128,127) - zp   (integer in [-255,255], exact fp16)
// ---------------------------------------------------------------------------
__global__ void __launch_bounds__(256) quant_x_kernel(const float* __restrict__ x) {
    const int row  = blockIdx.x * 8 + (threadIdx.x >> 5);
    const int lane = threadIdx.x & 31;
    const float4* xr4 = reinterpret_cast<const float4*>(x + (size_t)row * DIN);

    float4 v[16];                        // whole row held across the warp
#pragma unroll
    for (int i = 0; i < 16; i++) v[i] = xr4[lane + 32 * i];

    float mn = 0.0f, mx = 0.0f;          // init 0 implements min(.,0)/max(.,0)
#pragma unroll
    for (int i = 0; i < 16; i++) {
        mn = fminf(mn, fminf(fminf(v[i].x, v[i].y), fminf(v[i].z, v[i].w)));
        mx = fmaxf(mx, fmaxf(fmaxf(v[i].x, v[i].y), fmaxf(v[i].z, v[i].w)));
    }
#pragma unroll
    for (int o = 16; o; o >>= 1) {
        mn = fminf(mn, __shfl_xor_sync(0xffffffffu, mn, o));
        mx = fmaxf(mx, __shfl_xor_sync(0xffffffffu, mx, o));
    }
    float scale = __fdiv_rn(mx - mn, 255.0f);
    scale = fmaxf(scale, 1.1920929e-07f);          // float32 eps
    const float inv = __frcp_rn(scale);            // one reciprocal per row
    float zp = -128.0f - rintf(mn * inv);
    zp = fminf(fmaxf(zp, -128.0f), 127.0f);
    if (lane == 0) g_sx[row] = scale;

    uint2* qr = reinterpret_cast<uint2*>(g_qd + (size_t)row * DIN);
#pragma unroll
    for (int i = 0; i < 16; i++) {
        float q0 = fminf(fmaxf(rintf(v[i].x * inv) + zp, -128.0f), 127.0f) - zp;
        float q1 = fminf(fmaxf(rintf(v[i].y * inv) + zp, -128.0f), 127.0f) - zp;
        float q2 = fminf(fmaxf(rintf(v[i].z * inv) + zp, -128.0f), 127.0f) - zp;
        float q3 = fminf(fmaxf(rintf(v[i].w * inv) + zp, -128.0f), 127.0f) - zp;
        __half2 h0 = __floats2half2_rn(q0, q1);
        __half2 h1 = __floats2half2_rn(q2, q3);
        qr[lane + 32 * i] = make_uint2(*reinterpret_cast<uint32_t*>(&h0),
                                       *reinterpret_cast<uint32_t*>(&h1));
    }
}

// ---------------------------------------------------------------------------
// Kernel 2: grouped int4 weight dequant -> fp16
// ---------------------------------------------------------------------------
__global__ void __launch_bounds__(256) dequant_w_kernel(const int* __restrict__ w,
                                                        const float* __restrict__ s,
                                                        const float* __restrict__ z) {
    const int idx = blockIdx.x * 256 + threadIdx.x;
    const int e = idx * 4;
    if (e >= DOUT * DIN) return;
    const int o = e >> 11;                 // / DIN
    const int i = e & (DIN - 1);
    const int g = (o << 6) + (i >> 5);     // o*64 + i/32
    const float sc = s[g], zz = z[g];
    int4 wv = *reinterpret_cast<const int4*>(w + e);
    __half2 h0 = __floats2half2_rn(((float)wv.x - zz) * sc, ((float)wv.y - zz) * sc);
    __half2 h1 = __floats2half2_rn(((float)wv.z - zz) * sc, ((float)wv.w - zz) * sc);
    *reinterpret_cast<uint2*>(g_wdq + e) =
        make_uint2(*reinterpret_cast<uint32_t*>(&h0), *reinterpret_cast<uint32_t*>(&h1));
}

// ---------------------------------------------------------------------------
// Kernel 3: mma.sync fp16 GEMM, 3-stage cp.async, 2 CTAs/SM, 1 sync/chunk,
// B-fragment double buffering.
// ---------------------------------------------------------------------------
__device__ __forceinline__ uint32_t sw128(uint32_t off) {
    return off ^ ((off >> 3) & 0x70);      // bits[6:4] ^= bits[9:7]
}

__device__ __forceinline__ void cp_async16(uint32_t saddr, const void* gaddr) {
    asm volatile("cp.async.cg.shared.global [%0], [%1], 16;"
                 :: "r"(saddr), "l"(gaddr) : "memory");
}

// Load one K-chunk (A 128x64 + B 128x64 fp16) into stage `st`; always commits.
__device__ __forceinline__ void load_stage(uint32_t sbase, int st,
                                           const __half* gA, const __half* gB,
                                           int kt, int T) {
    if (kt < T) {
        const int tid = threadIdx.x;
        const int k0 = kt * BK;
#pragma unroll
        for (int it = 0; it < 8; it++) {
            int c = it * 256 + tid;            // 2048 chunks: 1024 A + 1024 B
            int isB = c >> 10;
            int cc = c & 1023;
            int row = cc >> 3, col = cc & 7;   // col: 16B chunk within 128B row
            const __half* src = (isB ? gB : gA) + (size_t)row * DIN + k0 + col * 8;
            uint32_t off = sw128((uint32_t)(row * 128 + col * 16));
            uint32_t dst = sbase + (isB ? SMEM_B_OFF : 0) + st * STAGE_A_BYTES + off;
            cp_async16(dst, src);
        }
    }
    asm volatile("cp.async.commit_group;" ::: "memory");
}

__device__ __forceinline__ void ld_bfrags(uint32_t bbase, int kb0, int wn, int lrow,
                                          uint32_t b[4][4]) {
#pragma unroll
    for (int nb = 0; nb < 4; nb++) {
        int row = wn * 64 + nb * 16 + lrow;
        uint32_t addr = bbase + sw128((uint32_t)(row * 128 + kb0));
        asm volatile("ldmatrix.sync.aligned.m8n8.x4.shared.b16 {%0,%1,%2,%3}, [%4];"
                     : "=r"(b[nb][0]), "=r"(b[nb][1]), "=r"(b[nb][2]), "=r"(b[nb][3])
                     : "r"(addr));
    }
}

__global__ void __launch_bounds__(TPB, 2)
gemm_f16_kernel(float* __restrict__ out) {
    extern __shared__ char smem[];
    const uint32_t sbase = (uint32_t)__cvta_generic_to_shared(smem);
    const int tid = threadIdx.x;
    const int lane = tid & 31, wid = tid >> 5;
    const int wm = wid & 3;                 // warp M index (x32)
    const int wn = wid >> 2;                // warp N index (x64)
    const int n0 = blockIdx.x * BN;
    const int m0 = blockIdx.y * BM;

    const __half* gA = g_qd + (size_t)m0 * DIN;
    const __half* gB = g_wdq + (size_t)n0 * DIN;
    const int T = DIN / BK;                 // 32

    load_stage(sbase, 0, gA, gB, 0, T);
    load_stage(sbase, 1, gA, gB, 1, T);

    float acc[2][8][4];
#pragma unroll
    for (int i = 0; i < 2; i++)
#pragma unroll
        for (int j = 0; j < 8; j++)
#pragma unroll
            for (int k = 0; k < 4; k++) acc[i][j][k] = 0.0f;

    // ldmatrix address pattern: lanes 0-7 rows+0 k+0 | 8-15 rows+8 k+0
    //                           lanes16-23 rows+0 k+16 | 24-31 rows+8 k+16
    const int lrow = (lane & 7) + ((lane >> 3) & 1) * 8;
    const int lkb  = (lane >> 4) * 16;

    uint32_t fb[2][4][4];                   // double-buffered B fragments

    int st = 0;
    for (int t = 0; t < T; t++) {
        asm volatile("cp.async.wait_group 1;" ::: "memory");
        __syncthreads();
        const uint32_t abase = sbase + st * STAGE_A_BYTES;
        const uint32_t bbase = sbase + SMEM_B_OFF + st * STAGE_A_BYTES;

        ld_bfrags(bbase, lkb, wn, lrow, fb[0]);

#pragma unroll
        for (int ks = 0; ks < 4; ks++) {
            const int kb = ks * 32 + lkb;
            uint32_t a[2][4];
#pragma unroll
            for (int mb = 0; mb < 2; mb++) {
                int row = wm * 32 + mb * 16 + lrow;
                uint32_t addr = abase + sw128((uint32_t)(row * 128 + kb));
                asm volatile("ldmatrix.sync.aligned.m8n8.x4.shared.b16 {%0,%1,%2,%3}, [%4];"
                             : "=r"(a[mb][0]), "=r"(a[mb][1]),
                               "=r"(a[mb][2]), "=r"(a[mb][3]) : "r"(addr));
            }
            if (ks < 3)
                ld_bfrags(bbase, (ks + 1) * 32 + lkb, wn, lrow, fb[(ks + 1) & 1]);
            uint32_t (*b)[4] = fb[ks & 1];
            // A frag {reg0..3}; B n8-block0 {reg0,reg2}, block1 {reg1,reg3}
#pragma unroll
            for (int mb = 0; mb < 2; mb++) {
#pragma unroll
                for (int nb = 0; nb < 4; nb++) {
#pragma unroll
                    for (int half = 0; half < 2; half++) {
                        float* c = acc[mb][nb * 2 + half];
                        asm volatile(
                            "mma.sync.aligned.m16n8k16.row.col.f32.f16.f16.f32 "
                            "{%0,%1,%2,%3}, {%4,%5,%6,%7}, {%8,%9}, {%0,%1,%2,%3};"
                            : "+f"(c[0]), "+f"(c[1]), "+f"(c[2]), "+f"(c[3])
                            : "r"(a[mb][0]), "r"(a[mb][1]),
                              "r"(a[mb][2]), "r"(a[mb][3]),
                              "r"(b[nb][half]), "r"(b[nb][half + 2]));
                    }
                }
            }
        }
        // Tail load: writes stage (t+2)%3 == (t-1)%3, only read by warps that
        // already passed this chunk's barrier; the load aliasing stage t sits
        // behind iteration t+1's barrier. One sync per chunk is sufficient.
        int nst = st + 2; if (nst >= STAGES) nst -= STAGES;
        load_stage(sbase, nst, gA, gB, t + 2, T);
        if (++st == STAGES) st = 0;
    }

    // Epilogue: scale by per-token scale, store
#pragma unroll
    for (int mb = 0; mb < 2; mb++) {
        const int mrow = m0 + wm * 32 + mb * 16 + (lane >> 2);
        const float sx0 = g_sx[mrow];
        const float sx1 = g_sx[mrow + 8];
        float* o0 = out + (size_t)mrow * DOUT + n0 + wn * 64 + (lane & 3) * 2;
        float* o1 = o0 + (size_t)8 * DOUT;
#pragma unroll
        for (int nb8 = 0; nb8 < 8; nb8++) {
            float* c = acc[mb][nb8];
            *reinterpret_cast<float2*>(o0 + nb8 * 8) = make_float2(c[0] * sx0, c[1] * sx0);
            *reinterpret_cast<float2*>(o1 + nb8 * 8) = make_float2(c[2] * sx1, c[3] * sx1);
        }
    }
}

// ---------------------------------------------------------------------------
extern "C" void kernel_launch(void* const* d_in, const int* in_sizes, int n_in,
                              void* d_out, int out_size) {
    const float* x     = (const float*)d_in[0];
    const int*   w_int = (const int*)d_in[1];
    const float* w_s   = (const float*)d_in[2];
    const float* w_z   = (const float*)d_in[3];
    float* out = (float*)d_out;

    const int M = in_sizes[0] / DIN;   // 8192 tokens

    cudaFuncSetAttribute(gemm_f16_kernel,
                         cudaFuncAttributeMaxDynamicSharedMemorySize, SMEM_TOTAL);

    quant_x_kernel<<<M / 8, 256>>>(x);
    dequant_w_kernel<<<(DOUT * DIN / 4 + 255) / 256, 256>>>(w_int, w_s, w_z);
    gemm_f16_kernel<<<dim3(DOUT / BN, M / BM), TPB, SMEM_TOTAL>>>(out);
}

// round 13
// speedup vs baseline: 2.6076x; 1.0069x over previous
#include <cuda_runtime.h>
#include <cuda_fp16.h>
#include <cstdint>

// Problem dims (fixed): x [4,2048,2048] f32, w_int [2048,2048] i32,
// w_scales/w_zeros [2048,64] f32. out [8192,2048] f32.
#define DIN    2048
#define DOUT   2048
#define MAXM   8192

#define BM 128
#define BN 128
#define BK 64                 // fp16 elems per chunk: 128 bytes per row
#define STAGES 3
#define TPB 256
#define GRIDX 296             // 2 persistent CTAs per SM x 148 SMs
#define NTILE ((MAXM / BM) * (DOUT / BN))   // 64 x 16 = 1024
#define STAGE_A_BYTES (BM * 128)      // 16 KB
#define STAGE_B_BYTES (BN * 128)      // 16 KB
#define SMEM_B_OFF (STAGES * STAGE_A_BYTES)
#define SMEM_TOTAL (STAGES * (STAGE_A_BYTES + STAGE_B_BYTES))   // 96 KB -> 2 CTAs/SM

// Scratch (__device__ globals: allocation-free rule)
__device__ __half g_qd[(size_t)MAXM * DIN];    // (q - zp): integer, exact in fp16
__device__ float  g_sx[MAXM];                  // per-token scale
__device__ __half g_wdq[(size_t)DOUT * DIN];   // dequantized weights fp16

// ---------------------------------------------------------------------------
// Kernel 1: per-token dynamic quant, one warp per row, row in registers,
// reciprocal-multiply instead of per-element division.
// qd = clip(rint(x/s)+zp,-128,127) - zp   (integer in [-255,255], exact fp16)
// ---------------------------------------------------------------------------
__global__ void __launch_bounds__(256) quant_x_kernel(const float* __restrict__ x) {
    const int row  = blockIdx.x * 8 + (threadIdx.x >> 5);
    const int lane = threadIdx.x & 31;
    const float4* xr4 = reinterpret_cast<const float4*>(x + (size_t)row * DIN);

    float4 v[16];                        // whole row held across the warp
#pragma unroll
    for (int i = 0; i < 16; i++) v[i] = xr4[lane + 32 * i];

    float mn = 0.0f, mx = 0.0f;          // init 0 implements min(.,0)/max(.,0)
#pragma unroll
    for (int i = 0; i < 16; i++) {
        mn = fminf(mn, fminf(fminf(v[i].x, v[i].y), fminf(v[i].z, v[i].w)));
        mx = fmaxf(mx, fmaxf(fmaxf(v[i].x, v[i].y), fmaxf(v[i].z, v[i].w)));
    }
#pragma unroll
    for (int o = 16; o; o >>= 1) {
        mn = fminf(mn, __shfl_xor_sync(0xffffffffu, mn, o));
        mx = fmaxf(mx, __shfl_xor_sync(0xffffffffu, mx, o));
    }
    float scale = __fdiv_rn(mx - mn, 255.0f);
    scale = fmaxf(scale, 1.1920929e-07f);          // float32 eps
    const float inv = __frcp_rn(scale);            // one reciprocal per row
    float zp = -128.0f - rintf(mn * inv);
    zp = fminf(fmaxf(zp, -128.0f), 127.0f);
    if (lane == 0) g_sx[row] = scale;

    uint2* qr = reinterpret_cast<uint2*>(g_qd + (size_t)row * DIN);
#pragma unroll
    for (int i = 0; i < 16; i++) {
        float q0 = fminf(fmaxf(rintf(v[i].x * inv) + zp, -128.0f), 127.0f) - zp;
        float q1 = fminf(fmaxf(rintf(v[i].y * inv) + zp, -128.0f), 127.0f) - zp;
        float q2 = fminf(fmaxf(rintf(v[i].z * inv) + zp, -128.0f), 127.0f) - zp;
        float q3 = fminf(fmaxf(rintf(v[i].w * inv) + zp, -128.0f), 127.0f) - zp;
        __half2 h0 = __floats2half2_rn(q0, q1);
        __half2 h1 = __floats2half2_rn(q2, q3);
        qr[lane + 32 * i] = make_uint2(*reinterpret_cast<uint32_t*>(&h0),
                                       *reinterpret_cast<uint32_t*>(&h1));
    }
}

// ---------------------------------------------------------------------------
// Kernel 2: grouped int4 weight dequant -> fp16
// ---------------------------------------------------------------------------
__global__ void __launch_bounds__(256) dequant_w_kernel(const int* __restrict__ w,
                                                        const float* __restrict__ s,
                                                        const float* __restrict__ z) {
    const int idx = blockIdx.x * 256 + threadIdx.x;
    const int e = idx * 4;
    if (e >= DOUT * DIN) return;
    const int o = e >> 11;                 // / DIN
    const int i = e & (DIN - 1);
    const int g = (o << 6) + (i >> 5);     // o*64 + i/32
    const float sc = s[g], zz = z[g];
    int4 wv = *reinterpret_cast<const int4*>(w + e);
    __half2 h0 = __floats2half2_rn(((float)wv.x - zz) * sc, ((float)wv.y - zz) * sc);
    __half2 h1 = __floats2half2_rn(((float)wv.z - zz) * sc, ((float)wv.w - zz) * sc);
    *reinterpret_cast<uint2*>(g_wdq + e) =
        make_uint2(*reinterpret_cast<uint32_t*>(&h0), *reinterpret_cast<uint32_t*>(&h1));
}

// ---------------------------------------------------------------------------
// Kernel 3: persistent mma.sync fp16 GEMM, 3-stage cp.async ring that streams
// seamlessly across tiles; 2 CTAs/SM; 1 sync per chunk.
// ---------------------------------------------------------------------------
__device__ __forceinline__ uint32_t sw128(uint32_t off) {
    return off ^ ((off >> 3) & 0x70);      // bits[6:4] ^= bits[9:7]
}

__device__ __forceinline__ void cp_async16(uint32_t saddr, const void* gaddr) {
    asm volatile("cp.async.cg.shared.global [%0], [%1], 16;"
                 :: "r"(saddr), "l"(gaddr) : "memory");
}

// Load one K-chunk (A 128x64 + B 128x64 fp16) into stage `st`; always commits.
// bound=0 disables the load (commit-only, keeps wait_group accounting aligned).
__device__ __forceinline__ void load_stage(uint32_t sbase, int st,
                                           const __half* gA, const __half* gB,
                                           int kt, int bound) {
    if (kt < bound) {
        const int tid = threadIdx.x;
        const int k0 = kt * BK;
#pragma unroll
        for (int it = 0; it < 8; it++) {
            int c = it * 256 + tid;            // 2048 chunks: 1024 A + 1024 B
            int isB = c >> 10;
            int cc = c & 1023;
            int row = cc >> 3, col = cc & 7;   // col: 16B chunk within 128B row
            const __half* src = (isB ? gB : gA) + (size_t)row * DIN + k0 + col * 8;
            uint32_t off = sw128((uint32_t)(row * 128 + col * 16));
            uint32_t dst = sbase + (isB ? SMEM_B_OFF : 0) + st * STAGE_A_BYTES + off;
            cp_async16(dst, src);
        }
    }
    asm volatile("cp.async.commit_group;" ::: "memory");
}

__device__ __forceinline__ void ld_bfrags(uint32_t bbase, int kb0, int wn, int lrow,
                                          uint32_t b[4][4]) {
#pragma unroll
    for (int nb = 0; nb < 4; nb++) {
        int row = wn * 64 + nb * 16 + lrow;
        uint32_t addr = bbase + sw128((uint32_t)(row * 128 + kb0));
        asm volatile("ldmatrix.sync.aligned.m8n8.x4.shared.b16 {%0,%1,%2,%3}, [%4];"
                     : "=r"(b[nb][0]), "=r"(b[nb][1]), "=r"(b[nb][2]), "=r"(b[nb][3])
                     : "r"(addr));
    }
}

__global__ void __launch_bounds__(TPB, 2)
gemm_f16_kernel(float* __restrict__ out) {
    extern __shared__ char smem[];
    const uint32_t sbase = (uint32_t)__cvta_generic_to_shared(smem);
    const int tid = threadIdx.x;
    const int lane = tid & 31, wid = tid >> 5;
    const int wm = wid & 3;                 // warp M index (x32)
    const int wn = wid >> 2;                // warp N index (x64)
    const int T = DIN / BK;                 // 32

    // ldmatrix address pattern: lanes 0-7 rows+0 k+0 | 8-15 rows+8 k+0
    //                           lanes16-23 rows+0 k+16 | 24-31 rows+8 k+16
    const int lrow = (lane & 7) + ((lane >> 3) & 1) * 8;
    const int lkb  = (lane >> 4) * 16;

    int tile = blockIdx.x;
    int m0 = (tile >> 4) * BM, n0 = (tile & 15) * BN;
    const __half* gA = g_qd + (size_t)m0 * DIN;
    const __half* gB = g_wdq + (size_t)n0 * DIN;

    load_stage(sbase, 0, gA, gB, 0, T);
    load_stage(sbase, 1, gA, gB, 1, T);

    int st = 0;
    while (true) {
        const int tile2 = tile + GRIDX;
        const __half* gA2 = g_qd;           // benign defaults (never loaded if
        const __half* gB2 = g_wdq;          //  bound=0 below)
        int bound2 = 0;
        if (tile2 < NTILE) {
            gA2 = g_qd + (size_t)((tile2 >> 4) * BM) * DIN;
            gB2 = g_wdq + (size_t)((tile2 & 15) * BN) * DIN;
            bound2 = T;
        }

        float acc[2][8][4];
#pragma unroll
        for (int i = 0; i < 2; i++)
#pragma unroll
            for (int j = 0; j < 8; j++)
#pragma unroll
                for (int k = 0; k < 4; k++) acc[i][j][k] = 0.0f;

        uint32_t fb[2][4][4];               // double-buffered B fragments

        for (int t = 0; t < T; t++) {
            asm volatile("cp.async.wait_group 1;" ::: "memory");
            __syncthreads();
            const uint32_t abase = sbase + st * STAGE_A_BYTES;
            const uint32_t bbase = sbase + SMEM_B_OFF + st * STAGE_A_BYTES;

            ld_bfrags(bbase, lkb, wn, lrow, fb[0]);

#pragma unroll
            for (int ks = 0; ks < 4; ks++) {
                const int kb = ks * 32 + lkb;
                uint32_t a[2][4];
#pragma unroll
                for (int mb = 0; mb < 2; mb++) {
                    int row = wm * 32 + mb * 16 + lrow;
                    uint32_t addr = abase + sw128((uint32_t)(row * 128 + kb));
                    asm volatile("ldmatrix.sync.aligned.m8n8.x4.shared.b16 {%0,%1,%2,%3}, [%4];"
                                 : "=r"(a[mb][0]), "=r"(a[mb][1]),
                                   "=r"(a[mb][2]), "=r"(a[mb][3]) : "r"(addr));
                }
                if (ks < 3)
                    ld_bfrags(bbase, (ks + 1) * 32 + lkb, wn, lrow, fb[(ks + 1) & 1]);
                uint32_t (*b)[4] = fb[ks & 1];
                // A frag {reg0..3}; B n8-block0 {reg0,reg2}, block1 {reg1,reg3}
#pragma unroll
                for (int mb = 0; mb < 2; mb++) {
#pragma unroll
                    for (int nb = 0; nb < 4; nb++) {
#pragma unroll
                        for (int half = 0; half < 2; half++) {
                            float* c = acc[mb][nb * 2 + half];
                            asm volatile(
                                "mma.sync.aligned.m16n8k16.row.col.f32.f16.f16.f32 "
                                "{%0,%1,%2,%3}, {%4,%5,%6,%7}, {%8,%9}, {%0,%1,%2,%3};"
                                : "+f"(c[0]), "+f"(c[1]), "+f"(c[2]), "+f"(c[3])
                                : "r"(a[mb][0]), "r"(a[mb][1]),
                                  "r"(a[mb][2]), "r"(a[mb][3]),
                                  "r"(b[nb][half]), "r"(b[nb][half + 2]));
                        }
                    }
                }
            }
            // Tail load: writes stage (st+2)%3 == stage (t-1)'s buffer, only
            // read by warps already past this chunk's barrier. When kt >= T it
            // streams the NEXT tile's chunk kt-T, so the epilogue below fully
            // overlaps the next tile's prologue. One sync per chunk suffices.
            const int kt = t + 2;
            int nst = st + 2; if (nst >= STAGES) nst -= STAGES;
            if (kt < T) load_stage(sbase, nst, gA, gB, kt, T);
            else        load_stage(sbase, nst, gA2, gB2, kt - T, bound2);
            if (++st == STAGES) st = 0;
        }

        // Epilogue: scale by per-token scale, store (overlaps next-tile loads)
#pragma unroll
        for (int mb = 0; mb < 2; mb++) {
            const int mrow = m0 + wm * 32 + mb * 16 + (lane >> 2);
            const float sx0 = g_sx[mrow];
            const float sx1 = g_sx[mrow + 8];
            float* o0 = out + (size_t)mrow * DOUT + n0 + wn * 64 + (lane & 3) * 2;
            float* o1 = o0 + (size_t)8 * DOUT;
#pragma unroll
            for (int nb8 = 0; nb8 < 8; nb8++) {
                float* c = acc[mb][nb8];
                *reinterpret_cast<float2*>(o0 + nb8 * 8) =
                    make_float2(c[0] * sx0, c[1] * sx0);
                *reinterpret_cast<float2*>(o1 + nb8 * 8) =
                    make_float2(c[2] * sx1, c[3] * sx1);
            }
        }

        if (tile2 >= NTILE) break;
        tile = tile2;
        m0 = (tile >> 4) * BM; n0 = (tile & 15) * BN;
        gA = gA2; gB = gB2;
    }
}

// ---------------------------------------------------------------------------
extern "C" void kernel_launch(void* const* d_in, const int* in_sizes, int n_in,
                              void* d_out, int out_size) {
    const float* x     = (const float*)d_in[0];
    const int*   w_int = (const int*)d_in[1];
    const float* w_s   = (const float*)d_in[2];
    const float* w_z   = (const float*)d_in[3];
    float* out = (float*)d_out;

    const int M = in_sizes[0] / DIN;   // 8192 tokens

    cudaFuncSetAttribute(gemm_f16_kernel,
                         cudaFuncAttributeMaxDynamicSharedMemorySize, SMEM_TOTAL);

    quant_x_kernel<<<M / 8, 256>>>(x);
    dequant_w_kernel<<<(DOUT * DIN / 4 + 255) / 256, 256>>>(w_int, w_s, w_z);
    gemm_f16_kernel<<<GRIDX, TPB, SMEM_TOTAL>>>(out);
}